// round 6
// baseline (speedup 1.0000x reference)
#include <cuda_runtime.h>
#include <cstdint>

#define DIM 4096
#define NTHREADS 256
#define GRID 1036   // 148 SMs * 7 CTAs

#define CP_ASYNC16(dst_u32, src_ptr) \
    asm volatile("cp.async.cg.shared.global [%0], [%1], 16;" \
                 :: "r"(dst_u32), "l"(src_ptr))
#define CP_COMMIT()  asm volatile("cp.async.commit_group;")
#define CP_WAIT1()   asm volatile("cp.async.wait_group 1;" ::: "memory")
#define CP_WAIT0()   asm volatile("cp.async.wait_group 0;" ::: "memory")

// Persistent-CTA FWHT-4096, double-buffered cp.async input pipeline.
// Buffer layout is globally swizzled: phys(L) = L ^ (((L>>6)&7)<<2)
// (16B-chunk granular -> applied at cp.async destination addressing).
// Per row: three in-place FWHT16 passes over dims
//   {e6..e9} (stride-64), {e2..e5} (stride-4), {e0,e1,e10,e11} (float4),
// all same-address read/modify/write, all bank-conflict-free.
__global__ void __launch_bounds__(NTHREADS, 7)
fwht4096_kernel(const float* __restrict__ x, float* __restrict__ out, int rows)
{
    __shared__ float buf[2][DIM];

    const int t = threadIdx.x;
    // swizzled float4 chunk base: (4t) ^ (((t>>4)&7)<<2)
    const int wb = (4 * t) ^ (((t >> 4) & 7) << 2);
    // pass-1 (stride-64) base
    const int base2 = (t & 63) + 1024 * (t >> 6);
    // pass-2 (stride-4) swizzled base
    const int P = ((t & 3) + 64 * ((t >> 2) & 15) + 1024 * (t >> 6))
                ^ (((t >> 2) & 7) << 2);

    const int row0 = blockIdx.x;
    const int stride = GRID;

    // prologue: prefetch first row into buf[0] (swizzled layout)
    {
        const float* src = x + (size_t)row0 * DIM + 4 * t;
        #pragma unroll
        for (int c = 0; c < 4; ++c) {
            uint32_t d = (uint32_t)__cvta_generic_to_shared(&buf[0][wb + 1024 * c]);
            CP_ASYNC16(d, src + 1024 * c);
        }
        CP_COMMIT();
    }

    int cur = 0;
    for (int row = row0; row < rows; row += stride, cur ^= 1) {
        // prefetch next row into the other buffer, then wait for this row
        const int nrow = row + stride;
        if (nrow < rows) {
            const float* src = x + (size_t)nrow * DIM + 4 * t;
            #pragma unroll
            for (int c = 0; c < 4; ++c) {
                uint32_t d = (uint32_t)__cvta_generic_to_shared(
                                 &buf[cur ^ 1][wb + 1024 * c]);
                CP_ASYNC16(d, src + 1024 * c);
            }
            CP_COMMIT();
            CP_WAIT1();
        } else {
            CP_WAIT0();
        }
        __syncthreads();

        float* __restrict__ sm = buf[cur];
        float v[16];

        // ---- pass 1: dims e6..e9 (stride-64 gather, swizzled, in-place) ----
        #pragma unroll
        for (int m = 0; m < 16; ++m)
            v[m] = sm[(base2 ^ (4 * (m & 7))) + 64 * m];
        #pragma unroll
        for (int s = 0; s < 4; ++s) {
            const int h = 1 << s;
            #pragma unroll
            for (int j = 0; j < 16; ++j) {
                if ((j & h) == 0) {
                    float a = v[j], b = v[j + h];
                    v[j] = a + b;  v[j + h] = a - b;
                }
            }
        }
        #pragma unroll
        for (int m = 0; m < 16; ++m)
            sm[(base2 ^ (4 * (m & 7))) + 64 * m] = v[m];
        __syncthreads();

        // ---- pass 2: dims e2..e5 (stride-4 gather, swizzled, in-place) ----
        #pragma unroll
        for (int n = 0; n < 16; ++n) v[n] = sm[P ^ (4 * n)];
        #pragma unroll
        for (int s = 0; s < 4; ++s) {
            const int h = 1 << s;
            #pragma unroll
            for (int j = 0; j < 16; ++j) {
                if ((j & h) == 0) {
                    float a = v[j], b = v[j + h];
                    v[j] = a + b;  v[j + h] = a - b;
                }
            }
        }
        #pragma unroll
        for (int n = 0; n < 16; ++n) sm[P ^ (4 * n)] = v[n];
        __syncthreads();

        // ---- pass 3: dims e0,e1,e10,e11 (float4 reads, swizzled) ----
        #pragma unroll
        for (int c = 0; c < 4; ++c) {
            float4 a = *reinterpret_cast<const float4*>(&sm[wb + 1024 * c]);
            v[4*c+0] = a.x; v[4*c+1] = a.y; v[4*c+2] = a.z; v[4*c+3] = a.w;
        }
        __syncthreads();   // all reads of this buffer done -> next iter may
                           // cp.async into it

        #pragma unroll
        for (int s = 0; s < 4; ++s) {
            const int h = 1 << s;
            #pragma unroll
            for (int j = 0; j < 16; ++j) {
                if ((j & h) == 0) {
                    float a = v[j], b = v[j + h];
                    v[j] = a + b;  v[j + h] = a - b;
                }
            }
        }

        // ---- scale (exact 1/64) + coalesced float4 stores ----
        const float SCALE = 0.015625f;
        float* __restrict__ po = out + (size_t)row * DIM + 4 * t;
        #pragma unroll
        for (int c = 0; c < 4; ++c) {
            float4 q = make_float4(v[4*c+0] * SCALE, v[4*c+1] * SCALE,
                                   v[4*c+2] * SCALE, v[4*c+3] * SCALE);
            *reinterpret_cast<float4*>(&po[1024 * c]) = q;
        }
    }
}

extern "C" void kernel_launch(void* const* d_in, const int* in_sizes, int n_in,
                              void* d_out, int out_size)
{
    const float* x = (const float*)d_in[0];
    float* out = (float*)d_out;
    const int rows = in_sizes[0] / DIM;   // 8192
    fwht4096_kernel<<<GRID, NTHREADS>>>(x, out, rows);
}

// round 9
// speedup vs baseline: 1.1285x; 1.1285x over previous
#include <cuda_runtime.h>
#include <cstdint>

#define DIM 4096
#define NTHREADS 256
#define GRID 888    // 148 SMs * 6 resident CTAs -> single wave, no tail wave

#define CP_ASYNC16(dst_u32, src_ptr) \
    asm volatile("cp.async.cg.shared.global [%0], [%1], 16;" \
                 :: "r"(dst_u32), "l"(src_ptr))
#define CP_COMMIT()  asm volatile("cp.async.commit_group;")
#define CP_WAIT1()   asm volatile("cp.async.wait_group 1;" ::: "memory")
#define CP_WAIT0()   asm volatile("cp.async.wait_group 0;" ::: "memory")

// Persistent-CTA FWHT-4096, double-buffered cp.async input pipeline.
// Buffer layout is globally swizzled: phys(L) = L ^ (((L>>6)&7)<<2)
// (16B-chunk granular -> applied for free at cp.async destination addressing).
// Per row: three in-place FWHT16 passes over dims
//   {e6..e9} (stride-64), {e2..e5} (stride-4), {e0,e1,e10,e11} (float4),
// all same-address per-thread read/modify/write, all bank-conflict-free.
__global__ void __launch_bounds__(NTHREADS, 6)
fwht4096_kernel(const float* __restrict__ x, float* __restrict__ out, int rows)
{
    __shared__ float buf[2][DIM];

    const int t = threadIdx.x;
    // swizzled float4 chunk base: (4t) ^ (((t>>4)&7)<<2)
    const int wb = (4 * t) ^ (((t >> 4) & 7) << 2);
    // pass-1 (stride-64) base
    const int base2 = (t & 63) + 1024 * (t >> 6);
    // pass-2 (stride-4) swizzled base
    const int P = ((t & 3) + 64 * ((t >> 2) & 15) + 1024 * (t >> 6))
                ^ (((t >> 2) & 7) << 2);

    const int row0 = blockIdx.x;

    // prologue: prefetch first row into buf[0] (swizzled layout)
    {
        const float* src = x + (size_t)row0 * DIM + 4 * t;
        #pragma unroll
        for (int c = 0; c < 4; ++c) {
            uint32_t d = (uint32_t)__cvta_generic_to_shared(&buf[0][wb + 1024 * c]);
            CP_ASYNC16(d, src + 1024 * c);
        }
        CP_COMMIT();
    }

    int cur = 0;
    for (int row = row0; row < rows; row += GRID, cur ^= 1) {
        // prefetch next row into the other buffer, then wait for this row
        const int nrow = row + GRID;
        if (nrow < rows) {
            const float* src = x + (size_t)nrow * DIM + 4 * t;
            #pragma unroll
            for (int c = 0; c < 4; ++c) {
                uint32_t d = (uint32_t)__cvta_generic_to_shared(
                                 &buf[cur ^ 1][wb + 1024 * c]);
                CP_ASYNC16(d, src + 1024 * c);
            }
            CP_COMMIT();
            CP_WAIT1();
        } else {
            CP_WAIT0();
        }
        __syncthreads();

        float* __restrict__ sm = buf[cur];
        float v[16];

        // ---- pass 1: dims e6..e9 (stride-64 gather, swizzled, in-place) ----
        #pragma unroll
        for (int m = 0; m < 16; ++m)
            v[m] = sm[(base2 ^ (4 * (m & 7))) + 64 * m];
        #pragma unroll
        for (int s = 0; s < 4; ++s) {
            const int h = 1 << s;
            #pragma unroll
            for (int j = 0; j < 16; ++j) {
                if ((j & h) == 0) {
                    float a = v[j], b = v[j + h];
                    v[j] = a + b;  v[j + h] = a - b;
                }
            }
        }
        #pragma unroll
        for (int m = 0; m < 16; ++m)
            sm[(base2 ^ (4 * (m & 7))) + 64 * m] = v[m];
        __syncthreads();

        // ---- pass 2: dims e2..e5 (stride-4 gather, swizzled, in-place) ----
        #pragma unroll
        for (int n = 0; n < 16; ++n) v[n] = sm[P ^ (4 * n)];
        #pragma unroll
        for (int s = 0; s < 4; ++s) {
            const int h = 1 << s;
            #pragma unroll
            for (int j = 0; j < 16; ++j) {
                if ((j & h) == 0) {
                    float a = v[j], b = v[j + h];
                    v[j] = a + b;  v[j + h] = a - b;
                }
            }
        }
        #pragma unroll
        for (int n = 0; n < 16; ++n) sm[P ^ (4 * n)] = v[n];
        __syncthreads();

        // ---- pass 3: dims e0,e1,e10,e11 (float4 reads, swizzled) ----
        #pragma unroll
        for (int c = 0; c < 4; ++c) {
            float4 a = *reinterpret_cast<const float4*>(&sm[wb + 1024 * c]);
            v[4*c+0] = a.x; v[4*c+1] = a.y; v[4*c+2] = a.z; v[4*c+3] = a.w;
        }
        __syncthreads();   // all reads of this buffer done -> next iteration's
                           // cp.async may overwrite it

        #pragma unroll
        for (int s = 0; s < 4; ++s) {
            const int h = 1 << s;
            #pragma unroll
            for (int j = 0; j < 16; ++j) {
                if ((j & h) == 0) {
                    float a = v[j], b = v[j + h];
                    v[j] = a + b;  v[j + h] = a - b;
                }
            }
        }

        // ---- scale (exact 1/64) + coalesced float4 stores ----
        const float SCALE = 0.015625f;
        float* __restrict__ po = out + (size_t)row * DIM + 4 * t;
        #pragma unroll
        for (int c = 0; c < 4; ++c) {
            float4 q = make_float4(v[4*c+0] * SCALE, v[4*c+1] * SCALE,
                                   v[4*c+2] * SCALE, v[4*c+3] * SCALE);
            *reinterpret_cast<float4*>(&po[1024 * c]) = q;
        }
    }
}

extern "C" void kernel_launch(void* const* d_in, const int* in_sizes, int n_in,
                              void* d_out, int out_size)
{
    const float* x = (const float*)d_in[0];
    float* out = (float*)d_out;
    const int rows = in_sizes[0] / DIM;   // 8192
    fwht4096_kernel<<<GRID, NTHREADS>>>(x, out, rows);
}